// round 5
// baseline (speedup 1.0000x reference)
#include <cuda_runtime.h>
#include <math.h>

#define BATCH 1024
#define DIM   128
#define N0    25
#define N1    10
#define NPB   250
#define FUSE_BLOCKS 32          // 32 blocks x 8 rows = 256 product rows

// g_act[b][0:128)=h0, [128:256)=mean idx1, [256:384)=mean leaf
__device__ __align__(16) float g_act[BATCH * 384];
// g_Wf rows 0..127 = W0a ; rows 128..383 = W1 @ W0b
__device__ __align__(16) float g_Wf[384 * 128];

// ---------------------------------------------------------------------------
// Kernel A: blocks 0..1023 gather+reduce; blocks 1024.. build fused weights.
// 256 threads.
// ---------------------------------------------------------------------------
__global__ __launch_bounds__(256) void gather_fuse_kernel(
    const float* __restrict__ embed,
    const float* __restrict__ W0,
    const float* __restrict__ W1,
    const int*   __restrict__ roots,
    const int*   __restrict__ idx1,
    const int*   __restrict__ idx2)
{
    __shared__ int   sIdx2[NPB];
    __shared__ int   sIdx1[N0];
    __shared__ __align__(16) float sRedA[8 * 128];     // leaf partials per warp
    __shared__ __align__(16) float sRedB[8 * 128];     // idx1 partials per warp
    __shared__ __align__(16) float sW1[8 * 128];       // fuse: 8 W1 rows
    __shared__ __align__(16) float sRedF[2 * 8 * 128]; // fuse: j-group partials

    const int tid = threadIdx.x;

    if (blockIdx.x < BATCH) {
        // ------------------ gather path ------------------
        const int b = blockIdx.x;
        const int w = tid >> 5;          // warp 0..7
        const int l = tid & 31;          // lane
        const int e = l * 4;             // float4 element offset in row

        if (tid < NPB) sIdx2[tid] = idx2[b * NPB + tid];
        if (tid < N0)  sIdx1[tid] = idx1[b * N0 + tid];
        __syncthreads();

        const float* E = embed + e;

        // leaf rows: warp w handles r = w, w+8, ... ; 8 loads in flight
        float4 a2 = make_float4(0.f, 0.f, 0.f, 0.f);
        int r = w;
        for (; r + 56 < NPB; r += 64) {
            float4 v[8];
#pragma unroll
            for (int u = 0; u < 8; u++)
                v[u] = *(const float4*)(E + (size_t)sIdx2[r + u * 8] * DIM);
#pragma unroll
            for (int u = 0; u < 8; u++) {
                a2.x += v[u].x; a2.y += v[u].y; a2.z += v[u].z; a2.w += v[u].w;
            }
        }
        for (; r < NPB; r += 8) {
            const float4 v = *(const float4*)(E + (size_t)sIdx2[r] * DIM);
            a2.x += v.x; a2.y += v.y; a2.z += v.z; a2.w += v.w;
        }

        // idx1 rows
        float4 a1 = make_float4(0.f, 0.f, 0.f, 0.f);
        for (int q = w; q < N0; q += 8) {
            const float4 v = *(const float4*)(E + (size_t)sIdx1[q] * DIM);
            a1.x += v.x; a1.y += v.y; a1.z += v.z; a1.w += v.w;
        }

        // root embedding: warp 0 writes straight through
        if (w == 0) {
            const float4 h0 = *(const float4*)(E + (size_t)__ldg(&roots[b]) * DIM);
            *(float4*)&g_act[b * 384 + e] = h0;
        }

        *(float4*)&sRedA[w * 128 + e] = a2;
        *(float4*)&sRedB[w * 128 + e] = a1;
        __syncthreads();

        if (tid < 128) {
            float s = 0.f;
#pragma unroll
            for (int j = 0; j < 8; j++) s += sRedB[j * 128 + tid];
            g_act[b * 384 + 128 + tid] = s * (1.0f / 25.0f);
        } else {
            const int dd = tid - 128;
            float s = 0.f;
#pragma unroll
            for (int j = 0; j < 8; j++) s += sRedA[j * 128 + dd];
            g_act[b * 384 + 256 + dd] = s * (1.0f / 250.0f);
        }
    } else {
        // ------------------ fuse path ------------------
        const int fb  = blockIdx.x - BATCH;      // 0..31
        const int kk0 = fb * 8;

        // copy W0a rows
        {
            const int base = fb * 512;
#pragma unroll
            for (int i = 0; i < 2; i++)
                g_Wf[base + tid + i * 256] = __ldg(&W0[base + tid + i * 256]);
        }

        // stage 8 rows of W1
        for (int i = tid; i < 1024; i += 256)
            sW1[i] = __ldg(&W1[kk0 * 128 + i]);
        __syncthreads();

        const int g = tid >> 7;      // j-group 0/1 (64 j each)
        const int d = tid & 127;

        float acc[8];
#pragma unroll
        for (int rr = 0; rr < 8; rr++) acc[rr] = 0.f;

        const int jbeg = g * 64;
        for (int j = 0; j < 64; j += 4) {
            float wv[4];
#pragma unroll
            for (int u = 0; u < 4; u++)
                wv[u] = __ldg(&W0[(size_t)(128 + jbeg + j + u) * 128 + d]);
#pragma unroll
            for (int u = 0; u < 4; u++) {
#pragma unroll
                for (int rr = 0; rr < 8; rr++)
                    acc[rr] = fmaf(sW1[rr * 128 + jbeg + j + u], wv[u], acc[rr]);
            }
        }

#pragma unroll
        for (int rr = 0; rr < 8; rr++)
            sRedF[g * 1024 + rr * 128 + d] = acc[rr];
        __syncthreads();

        if (g == 0) {
#pragma unroll
            for (int rr = 0; rr < 8; rr++)
                g_Wf[(size_t)(128 + kk0 + rr) * 128 + d] =
                    sRedF[rr * 128 + d] + sRedF[1024 + rr * 128 + d];
        }
    }
}

// ---------------------------------------------------------------------------
// Kernel B: out = sigmoid(g_act @ g_Wf + b0).
// grid = 128 row-blocks x 4 col-blocks = 512. block = 256 threads.
// col tile = 32 output dims. dl = tid&31, kg = tid>>5 (8 k-groups of 48).
// ---------------------------------------------------------------------------
__global__ __launch_bounds__(256) void mlp_kernel(
    const float* __restrict__ b0,
    float*       __restrict__ out)
{
    __shared__ __align__(16) float sActT[384 * 8];       // [k][r], 12 KB
    __shared__ __align__(16) float sRed[8 * 8 * 32];     // [kg][r][dl], 8 KB

    const int tid  = threadIdx.x;
    const int dl   = tid & 31;
    const int kg   = tid >> 5;
    const int col0 = (blockIdx.x & 3) * 32;
    const int row0 = (blockIdx.x >> 2) * 8;
    const int d    = col0 + dl;

    // stage transposed activations for 8 rows
    for (int i = tid; i < 8 * 384; i += 256) {
        const int r = i / 384;
        const int k = i - r * 384;
        sActT[k * 8 + r] = g_act[(size_t)(row0 + r) * 384 + k];
    }
    __syncthreads();

    float acc[8];
#pragma unroll
    for (int r = 0; r < 8; r++) acc[r] = 0.f;

    const int kbeg = kg * 48;
    for (int k = 0; k < 48; k += 8) {
        float wv[8];
#pragma unroll
        for (int u = 0; u < 8; u++)
            wv[u] = __ldg(&g_Wf[(size_t)(kbeg + k + u) * 128 + d]);
#pragma unroll
        for (int u = 0; u < 8; u++) {
            const float4 aLo = *(const float4*)&sActT[(kbeg + k + u) * 8];
            const float4 aHi = *(const float4*)&sActT[(kbeg + k + u) * 8 + 4];
            acc[0] = fmaf(aLo.x, wv[u], acc[0]);
            acc[1] = fmaf(aLo.y, wv[u], acc[1]);
            acc[2] = fmaf(aLo.z, wv[u], acc[2]);
            acc[3] = fmaf(aLo.w, wv[u], acc[3]);
            acc[4] = fmaf(aHi.x, wv[u], acc[4]);
            acc[5] = fmaf(aHi.y, wv[u], acc[5]);
            acc[6] = fmaf(aHi.z, wv[u], acc[6]);
            acc[7] = fmaf(aHi.w, wv[u], acc[7]);
        }
    }

#pragma unroll
    for (int r = 0; r < 8; r++)
        sRed[kg * 256 + r * 32 + dl] = acc[r];
    __syncthreads();

    if (kg == 0) {
        const float bb = __ldg(&b0[d]);
#pragma unroll
        for (int r = 0; r < 8; r++) {
            float s = bb;
#pragma unroll
            for (int j = 0; j < 8; j++)
                s += sRed[j * 256 + r * 32 + dl];
            out[(size_t)(row0 + r) * 128 + d] = 1.0f / (1.0f + __expf(-s));
        }
    }
}

// ---------------------------------------------------------------------------
// Inputs: embed_table, W0, b0, W1, roots, idx1, idx2
// ---------------------------------------------------------------------------
extern "C" void kernel_launch(void* const* d_in, const int* in_sizes, int n_in,
                              void* d_out, int out_size)
{
    const float* embed = (const float*)d_in[0];
    const float* W0    = (const float*)d_in[1];
    const float* b0    = (const float*)d_in[2];
    const float* W1    = (const float*)d_in[3];
    const int*   roots = (const int*)  d_in[4];
    const int*   idx1  = (const int*)  d_in[5];
    const int*   idx2  = (const int*)  d_in[6];
    float*       out   = (float*)d_out;

    gather_fuse_kernel<<<BATCH + FUSE_BLOCKS, 256>>>(embed, W0, W1, roots, idx1, idx2);
    mlp_kernel<<<512, 256>>>(b0, out);
}

// round 7
// speedup vs baseline: 1.1682x; 1.1682x over previous
#include <cuda_runtime.h>
#include <stdint.h>
#include <math.h>

#define BATCH 1024
#define DIM   128
#define N0    25
#define N1    10
#define NPB   250
#define FUSE_BLOCKS 32          // 32 blocks x 8 rows = 256 product rows

// g_act[b][0:128)=h0, [128:256)=mean idx1, [256:384)=mean leaf
__device__ __align__(16) float g_act[BATCH * 384];
// g_Wf rows 0..127 = W0a ; rows 128..383 = W1 @ W0b
__device__ __align__(16) float g_Wf[384 * 128];

__device__ __forceinline__ void cp_async16(uint32_t saddr, const void* gptr) {
    asm volatile("cp.async.cg.shared.global [%0], [%1], 16;" :: "r"(saddr), "l"(gptr));
}
__device__ __forceinline__ void cp_commit() {
    asm volatile("cp.async.commit_group;");
}
template <int N>
__device__ __forceinline__ void cp_wait() {
    asm volatile("cp.async.wait_group %0;" :: "n"(N));
}

// ---------------------------------------------------------------------------
// Kernel A: blocks 0..1023 gather+reduce; blocks 1024.. build fused weights.
// 256 threads. (identical to round-4 version)
// ---------------------------------------------------------------------------
__global__ __launch_bounds__(256) void gather_fuse_kernel(
    const float* __restrict__ embed,
    const float* __restrict__ W0,
    const float* __restrict__ W1,
    const int*   __restrict__ roots,
    const int*   __restrict__ idx1,
    const int*   __restrict__ idx2)
{
    __shared__ int   sIdx2[NPB];
    __shared__ int   sIdx1[N0];
    __shared__ __align__(16) float sRedA[8 * 128];
    __shared__ __align__(16) float sRedB[8 * 128];
    __shared__ __align__(16) float sW1[8 * 128];
    __shared__ __align__(16) float sRedF[2 * 8 * 128];

    const int tid = threadIdx.x;

    if (blockIdx.x < BATCH) {
        const int b = blockIdx.x;
        const int w = tid >> 5;
        const int l = tid & 31;
        const int e = l * 4;

        if (tid < NPB) sIdx2[tid] = idx2[b * NPB + tid];
        if (tid < N0)  sIdx1[tid] = idx1[b * N0 + tid];
        __syncthreads();

        const float* E = embed + e;

        float4 a2 = make_float4(0.f, 0.f, 0.f, 0.f);
        int r = w;
        for (; r + 24 < NPB; r += 32) {
            const float4 v0 = *(const float4*)(E + (size_t)sIdx2[r     ] * DIM);
            const float4 v1 = *(const float4*)(E + (size_t)sIdx2[r +  8] * DIM);
            const float4 v2 = *(const float4*)(E + (size_t)sIdx2[r + 16] * DIM);
            const float4 v3 = *(const float4*)(E + (size_t)sIdx2[r + 24] * DIM);
            a2.x += (v0.x + v1.x) + (v2.x + v3.x);
            a2.y += (v0.y + v1.y) + (v2.y + v3.y);
            a2.z += (v0.z + v1.z) + (v2.z + v3.z);
            a2.w += (v0.w + v1.w) + (v2.w + v3.w);
        }
        for (; r < NPB; r += 8) {
            const float4 v = *(const float4*)(E + (size_t)sIdx2[r] * DIM);
            a2.x += v.x; a2.y += v.y; a2.z += v.z; a2.w += v.w;
        }

        float4 a1 = make_float4(0.f, 0.f, 0.f, 0.f);
        for (int q = w; q < N0; q += 8) {
            const float4 v = *(const float4*)(E + (size_t)sIdx1[q] * DIM);
            a1.x += v.x; a1.y += v.y; a1.z += v.z; a1.w += v.w;
        }

        if (w == 0) {
            const float4 h0 = *(const float4*)(E + (size_t)__ldg(&roots[b]) * DIM);
            *(float4*)&g_act[b * 384 + e] = h0;
        }

        *(float4*)&sRedA[w * 128 + e] = a2;
        *(float4*)&sRedB[w * 128 + e] = a1;
        __syncthreads();

        if (tid < 128) {
            float s = 0.f;
#pragma unroll
            for (int j = 0; j < 8; j++) s += sRedB[j * 128 + tid];
            g_act[b * 384 + 128 + tid] = s * (1.0f / 25.0f);
        } else {
            const int dd = tid - 128;
            float s = 0.f;
#pragma unroll
            for (int j = 0; j < 8; j++) s += sRedA[j * 128 + dd];
            g_act[b * 384 + 256 + dd] = s * (1.0f / 250.0f);
        }
    } else {
        const int fb  = blockIdx.x - BATCH;
        const int kk0 = fb * 8;

        {
            const int base = fb * 512;
#pragma unroll
            for (int i = 0; i < 2; i++)
                g_Wf[base + tid + i * 256] = __ldg(&W0[base + tid + i * 256]);
        }

        for (int i = tid; i < 1024; i += 256)
            sW1[i] = __ldg(&W1[kk0 * 128 + i]);
        __syncthreads();

        const int g = tid >> 7;
        const int d = tid & 127;

        float acc[8];
#pragma unroll
        for (int rr = 0; rr < 8; rr++) acc[rr] = 0.f;

        const int jbeg = g * 64;
        for (int j = 0; j < 64; j += 4) {
            float wv[4];
#pragma unroll
            for (int u = 0; u < 4; u++)
                wv[u] = __ldg(&W0[(size_t)(128 + jbeg + j + u) * 128 + d]);
#pragma unroll
            for (int u = 0; u < 4; u++) {
#pragma unroll
                for (int rr = 0; rr < 8; rr++)
                    acc[rr] = fmaf(sW1[rr * 128 + jbeg + j + u], wv[u], acc[rr]);
            }
        }

#pragma unroll
        for (int rr = 0; rr < 8; rr++)
            sRedF[g * 1024 + rr * 128 + d] = acc[rr];
        __syncthreads();

        if (g == 0) {
#pragma unroll
            for (int rr = 0; rr < 8; rr++)
                g_Wf[(size_t)(128 + kk0 + rr) * 128 + d] =
                    sRedF[rr * 128 + d] + sRedF[1024 + rr * 128 + d];
        }
    }
}

// ---------------------------------------------------------------------------
// Kernel B: out = sigmoid(g_act @ g_Wf + b0).
// grid=128, block=512, 8 rows/block. d = tid&127, kg = tid>>7 (4 k-groups).
// Weights streamed through shared memory with cp.async double buffering:
// 24 chunks of 16 k. Per chunk each thread copies exactly one 16B quad.
// ---------------------------------------------------------------------------
#define KCH 16                       // k per chunk
#define NCH (384 / KCH)              // 24 chunks
#define CHF (KCH * 128)              // floats per chunk = 2048

__global__ __launch_bounds__(512) void mlp_kernel(
    const float* __restrict__ b0,
    float*       __restrict__ out)
{
    __shared__ __align__(16) float sActT[384 * 8];     // [k][r], 12 KB
    __shared__ __align__(16) float sW[2][CHF];          // 2 x 8 KB
    __shared__ __align__(16) float sRed[4 * 8 * 128];   // 16 KB

    const int tid  = threadIdx.x;
    const int d    = tid & 127;
    const int kg   = tid >> 7;
    const int row0 = blockIdx.x * 8;

    const uint32_t sw0 = (uint32_t)__cvta_generic_to_shared(&sW[0][0]);
    const uint32_t sw1 = (uint32_t)__cvta_generic_to_shared(&sW[1][0]);

    // prefetch chunk 0 (one 16B quad per thread)
    cp_async16(sw0 + tid * 16, g_Wf + tid * 4);
    cp_commit();

    // stage transposed activations for 8 rows
    for (int i = tid; i < 8 * 384; i += 512) {
        const int r = i / 384;
        const int k = i - r * 384;
        sActT[k * 8 + r] = g_act[(size_t)(row0 + r) * 384 + k];
    }

    float acc[8];
#pragma unroll
    for (int r = 0; r < 8; r++) acc[r] = 0.f;

    for (int c = 0; c < NCH; c++) {
        if (c + 1 < NCH) {
            const uint32_t dst = ((c + 1) & 1) ? sw1 : sw0;
            cp_async16(dst + tid * 16, g_Wf + (size_t)(c + 1) * CHF + tid * 4);
            cp_commit();
            cp_wait<1>();
        } else {
            cp_wait<0>();
        }
        __syncthreads();   // chunk c visible to all; also guards sActT on c==0

        const float* W = (c & 1) ? sW[1] : sW[0];
        const int kb = kg * (KCH / 4);            // 4 k per group within chunk
#pragma unroll
        for (int kk = 0; kk < KCH / 4; kk++) {
            const int kl = kb + kk;               // local k in chunk
            const int k  = c * KCH + kl;          // global k
            const float w = W[kl * 128 + d];
            const float4 aLo = *(const float4*)&sActT[k * 8];
            const float4 aHi = *(const float4*)&sActT[k * 8 + 4];
            acc[0] = fmaf(aLo.x, w, acc[0]);
            acc[1] = fmaf(aLo.y, w, acc[1]);
            acc[2] = fmaf(aLo.z, w, acc[2]);
            acc[3] = fmaf(aLo.w, w, acc[3]);
            acc[4] = fmaf(aHi.x, w, acc[4]);
            acc[5] = fmaf(aHi.y, w, acc[5]);
            acc[6] = fmaf(aHi.z, w, acc[6]);
            acc[7] = fmaf(aHi.w, w, acc[7]);
        }
        __syncthreads();   // done reading buffer before it is refilled
    }

#pragma unroll
    for (int r = 0; r < 8; r++)
        sRed[kg * 1024 + r * 128 + d] = acc[r];
    __syncthreads();

    if (kg == 0) {
        const float bb = __ldg(&b0[d]);
#pragma unroll
        for (int r = 0; r < 8; r++) {
            const float s = sRed[r * 128 + d] + sRed[1024 + r * 128 + d]
                          + sRed[2048 + r * 128 + d] + sRed[3072 + r * 128 + d] + bb;
            out[(size_t)(row0 + r) * 128 + d] = 1.0f / (1.0f + __expf(-s));
        }
    }
}

// ---------------------------------------------------------------------------
// Inputs: embed_table, W0, b0, W1, roots, idx1, idx2
// ---------------------------------------------------------------------------
extern "C" void kernel_launch(void* const* d_in, const int* in_sizes, int n_in,
                              void* d_out, int out_size)
{
    const float* embed = (const float*)d_in[0];
    const float* W0    = (const float*)d_in[1];
    const float* b0    = (const float*)d_in[2];
    const float* W1    = (const float*)d_in[3];
    const int*   roots = (const int*)  d_in[4];
    const int*   idx1  = (const int*)  d_in[5];
    const int*   idx2  = (const int*)  d_in[6];
    float*       out   = (float*)d_out;

    gather_fuse_kernel<<<BATCH + FUSE_BLOCKS, 256>>>(embed, W0, W1, roots, idx1, idx2);
    mlp_kernel<<<BATCH / 8, 512>>>(b0, out);
}